// round 17
// baseline (speedup 1.0000x reference)
#include <cuda_runtime.h>
#include <cuda_fp16.h>
#include <cstdint>

typedef unsigned long long ull;

#define BATCH 8
#define CH    64
#define MID   8
#define NPIX  4096
#define TQ    128
#define TJ    128

// Scratch (no allocations allowed -> __device__ globals)
__device__ __half g_q[BATCH * NPIX * MID];  // [b][i][m'] slots (m0,m4,m1,m5,m2,m6,m3,m7), pre-scaled log2e
__device__ __half g_k[BATCH * NPIX * MID];  // [b][j][m'] same interleave
__device__ __half g_v[BATCH * NPIX * CH];   // [b][n][c]  j-major fp16
__device__ unsigned g_bar = 0;              // device-wide barrier ticket (monotonic)

// ---------------------------------------------------------------------------
// helpers
// ---------------------------------------------------------------------------
__device__ __forceinline__ uint32_t smem_u32(const void* p) {
    uint32_t a;
    asm("{ .reg .u64 t; cvta.to.shared.u64 t, %1; cvt.u32.u64 %0, t; }"
        : "=r"(a) : "l"(p));
    return a;
}
__device__ __forceinline__ void cp_async16(uint32_t dst, const void* src) {
    asm volatile("cp.async.cg.shared.global [%0], [%1], 16;"
                 :: "r"(dst), "l"(src) : "memory");
}
#define CP_COMMIT()  asm volatile("cp.async.commit_group;" ::: "memory")
#define CP_WAIT0()   asm volatile("cp.async.wait_group 0;" ::: "memory")

__device__ __forceinline__ float ex2(float f) {
    float r;
    asm("ex2.approx.f32 %0, %1;" : "=f"(r) : "f"(f));
    return r;
}
// pack two f32 -> f16x2 (lo = first arg in low half)
__device__ __forceinline__ uint32_t packh(float lo, float hi) {
    uint32_t d;
    asm("cvt.rn.f16x2.f32 %0, %1, %2;" : "=r"(d) : "f"(hi), "f"(lo));
    return d;
}

// m16n8k8 fp16 MMA, f32 accum (for S)
__device__ __forceinline__ void mma_f16k8(float* d, uint32_t a0, uint32_t a1,
                                          uint32_t b0) {
    asm volatile(
        "mma.sync.aligned.m16n8k8.row.col.f32.f16.f16.f32 "
        "{%0,%1,%2,%3}, {%4,%5}, {%6}, {%0,%1,%2,%3};"
        : "+f"(d[0]), "+f"(d[1]), "+f"(d[2]), "+f"(d[3])
        : "r"(a0), "r"(a1), "r"(b0));
}
// m16n8k16 fp16 MMA, f32 accum (for PV)
__device__ __forceinline__ void mma_f16(float* d,
                                        uint32_t a0, uint32_t a1,
                                        uint32_t a2, uint32_t a3,
                                        uint32_t b0, uint32_t b1) {
    asm volatile(
        "mma.sync.aligned.m16n8k16.row.col.f32.f16.f16.f32 "
        "{%0,%1,%2,%3}, {%4,%5,%6,%7}, {%8,%9}, {%0,%1,%2,%3};"
        : "+f"(d[0]), "+f"(d[1]), "+f"(d[2]), "+f"(d[3])
        : "r"(a0), "r"(a1), "r"(a2), "r"(a3), "r"(b0), "r"(b1));
}
// ldmatrix x4 transposed (B-operand loader)
__device__ __forceinline__ void ldsm_x4t(uint32_t& r0, uint32_t& r1,
                                         uint32_t& r2, uint32_t& r3,
                                         uint32_t addr) {
    asm volatile(
        "ldmatrix.sync.aligned.m8n8.x4.trans.shared.b16 {%0,%1,%2,%3}, [%4];"
        : "=r"(r0), "=r"(r1), "=r"(r2), "=r"(r3) : "r"(addr));
}

#define FMA_X2(acc, a, bb) \
    asm("fma.rn.f32x2 %0, %1, %2, %0;" : "+l"(acc) : "l"(a), "l"(bb))

// ---------------------------------------------------------------------------
// Fused kernel: phase 1 projection (2 threads/pixel), device-wide barrier,
// phase 2 attention (identical structure to R16, Z via scalar FADD).
// ---------------------------------------------------------------------------
// attention-phase dyn smem byte offsets:
#define VB0 0u          // 128 * 144 = 18432
#define KB0 18432u      // 128 * 16  = 2048
#define VB1 20480u
#define KB1 38912u
#define SMEM_BYTES 40960
#define ZOFF 8256       // float index (epilogue staging reuses ring)

__device__ __forceinline__ void prefetch_tile(uint32_t sm, uint32_t vbyte,
                                              uint32_t kbyte,
                                              const __half* vg,
                                              const __half* kg,
                                              int j0, int tid)
{
    // V tile: 128 j-rows x 64 halves (128B each) -> smem stride 144B
    #pragma unroll
    for (int u = 0; u < 4; u++) {
        int idx = u * 256 + tid;          // 0..1023
        int j = idx >> 3, ch = idx & 7;
        cp_async16(sm + vbyte + (uint32_t)(j * 144 + ch * 16),
                   vg + (size_t)(j0 + j) * CH + ch * 8);
    }
    // K tile: 128 j-rows x 8 halves (16B each)
    if (tid < 128)
        cp_async16(sm + kbyte + (uint32_t)tid * 16,
                   kg + (size_t)(j0 + tid) * MID);
}

__global__ __launch_bounds__(256, 2) void fused_kernel(
    const float* __restrict__ x,
    const float* __restrict__ wq, const float* __restrict__ bq,
    const float* __restrict__ wk, const float* __restrict__ bk,
    const float* __restrict__ wv, const float* __restrict__ bv,
    const float* __restrict__ gamma,
    float* __restrict__ out)
{
    extern __shared__ __align__(128) float smem[];
    const uint32_t sm = smem_u32(smem);
    const int tid = threadIdx.x;

    // =====================================================================
    // Phase 1: projection. This block handles 128 pixels, 2 threads each.
    //   h==0 thread: q (log2e-scaled, interleaved) + v channels [0,32)
    //   h==1 thread: k (interleaved)               + v channels [32,64)
    // =====================================================================
    {
        float* s_wvT = smem;           // [c][d] 4096
        float* s_wqT = smem + 4096;    // [c][m] 512
        float* s_wkT = smem + 4608;    // [c][m] 512
        float* s_b   = smem + 5120;    // bq[8] bk[8] bv[64]

        for (int idx = tid; idx < CH * CH; idx += 256) {
            int d = idx >> 6, c = idx & 63;
            s_wvT[c * CH + d] = wv[idx];
        }
        for (int idx = tid; idx < MID * CH; idx += 256) {
            int m = idx >> 6, c = idx & 63;
            s_wqT[c * MID + m] = wq[idx];
            s_wkT[c * MID + m] = wk[idx];
        }
        if (tid < MID)      s_b[tid] = bq[tid];
        else if (tid < 16)  s_b[tid] = bk[tid - 8];
        else if (tid < 80)  s_b[tid] = bv[tid - 16];
        __syncthreads();

        const int bl = blockIdx.y * 32 + blockIdx.x;     // 0..255
        const int gp = bl * 128 + (tid >> 1);            // pixel id
        const int pb = gp >> 12, pn = gp & (NPIX - 1);
        const int h  = tid & 1;

        float qk[MID];
        ull vacc[16];
        const float* wqkT = h ? s_wkT : s_wqT;
        const float* bqk  = h ? s_b + 8 : s_b;
        #pragma unroll
        for (int m = 0; m < MID; m++) qk[m] = bqk[m];
        #pragma unroll
        for (int dd = 0; dd < 16; dd++)
            vacc[dd] = *(const ull*)&s_b[16 + h * 32 + 2 * dd];

        const float* xp = x + (size_t)pb * CH * NPIX + pn;
        const int vco = h * 32;
        for (int c = 0; c < CH; c++) {
            float xv = xp[(size_t)c * NPIX];
            ull xv2;
            asm("mov.b64 %0, {%1, %1};" : "=l"(xv2) : "r"(__float_as_uint(xv)));
            #pragma unroll
            for (int m = 0; m < MID; m++)
                qk[m] = fmaf(wqkT[c * MID + m], xv, qk[m]);
            #pragma unroll
            for (int dd = 0; dd < 16; dd++) {
                ull w2 = *(const ull*)&s_wvT[c * CH + vco + 2 * dd];
                FMA_X2(vacc[dd], w2, xv2);
            }
        }

        const float LOG2E = 1.4426950408889634f;
        uint4 o;
        if (h == 0) {
            o.x = packh(qk[0] * LOG2E, qk[4] * LOG2E);
            o.y = packh(qk[1] * LOG2E, qk[5] * LOG2E);
            o.z = packh(qk[2] * LOG2E, qk[6] * LOG2E);
            o.w = packh(qk[3] * LOG2E, qk[7] * LOG2E);
            *(uint4*)&g_q[(size_t)gp * MID] = o;
        } else {
            o.x = packh(qk[0], qk[4]);
            o.y = packh(qk[1], qk[5]);
            o.z = packh(qk[2], qk[6]);
            o.w = packh(qk[3], qk[7]);
            *(uint4*)&g_k[(size_t)gp * MID] = o;
        }
        __half* vo = g_v + (size_t)gp * CH + vco;
        #pragma unroll
        for (int r = 0; r < 2; r++) {
            uint4 w;
            float2 p0 = *(float2*)&vacc[r * 8 + 0];
            float2 p1 = *(float2*)&vacc[r * 8 + 1];
            float2 p2 = *(float2*)&vacc[r * 8 + 2];
            float2 p3 = *(float2*)&vacc[r * 8 + 3];
            w.x = packh(p0.x, p0.y); w.y = packh(p1.x, p1.y);
            w.z = packh(p2.x, p2.y); w.w = packh(p3.x, p3.y);
            *(uint4*)(vo + r * 16) = w;
            float2 p4 = *(float2*)&vacc[r * 8 + 4];
            float2 p5 = *(float2*)&vacc[r * 8 + 5];
            float2 p6 = *(float2*)&vacc[r * 8 + 6];
            float2 p7 = *(float2*)&vacc[r * 8 + 7];
            w.x = packh(p4.x, p4.y); w.y = packh(p5.x, p5.y);
            w.z = packh(p6.x, p6.y); w.w = packh(p7.x, p7.y);
            *(uint4*)(vo + r * 16 + 8) = w;
        }
    }

    // =====================================================================
    // Device-wide barrier (monotonic ticket; all 256 blocks co-resident:
    // 2 blocks/SM x 148 SMs = 296 slots >= 256, so no deadlock).
    // =====================================================================
    __threadfence();
    __syncthreads();
    if (tid == 0) {
        unsigned t = atomicAdd(&g_bar, 1u);
        unsigned target = (t & ~255u) + 256u;
        while (*(volatile unsigned*)&g_bar < target) __nanosleep(64);
    }
    __syncthreads();
    __threadfence();

    // =====================================================================
    // Phase 2: attention. Warp w owns i-rows [16w, 16w+16).
    // Per 128-j tile, per warp (8 chunks of 16 j):
    //   2x S-MMA fp16 k8 (C init = -16), 8x ex2 -> e = 2^(s'-16),
    //   Z += e (scalar FADD, fma pipe), 4x f16x2 pack,
    //   4x ldmatrix.x4.trans -> 8x PV-MMA fp16 k16.
    // =====================================================================
    const char* smc = (const char*)smem;
    const int wid = tid >> 5;
    const int lid = tid & 31;
    const int g8  = lid >> 2;
    const int tig = lid & 3;
    const int b   = blockIdx.y;
    const int i0g = blockIdx.x * TQ;

    const int ia = i0g + wid * 16 + g8;
    const __half* qh = g_q + ((size_t)b * NPIX + ia) * MID;
    const uint32_t qa0 = *(const uint32_t*)(qh + 2 * tig);
    const uint32_t qa1 = *(const uint32_t*)(qh + 8 * MID + 2 * tig);

    const int sel  = lid >> 3;
    const int joff = ((sel & 1) << 3) + (lid & 7);
    const int coff = (sel >> 1) << 3;
    const uint32_t lm_off = (uint32_t)(joff * 144 + coff * 2);

    float acc[8][4];
    #pragma unroll
    for (int ng = 0; ng < 8; ng++)
        #pragma unroll
        for (int r = 0; r < 4; r++) acc[ng][r] = 0.0f;
    float zr0 = 0.0f, zr1 = 0.0f;

    const __half* vb = g_v + (size_t)b * NPIX * CH;
    const __half* kb = g_k + (size_t)b * NPIX * MID;
    const float NS = -16.0f;              // exponent shift (cancels in num/Z)

    prefetch_tile(sm, VB0, KB0, vb, kb, 0, tid);
    CP_COMMIT();

    for (int t = 0; t < NPIX / TJ; t++) {
        CP_WAIT0();
        __syncthreads();
        if (t + 1 < NPIX / TJ) {
            prefetch_tile(sm, (t & 1) ? VB0 : VB1, (t & 1) ? KB0 : KB1,
                          vb, kb, (t + 1) * TJ, tid);
            CP_COMMIT();
        }
        const uint32_t vbuf = sm + ((t & 1) ? VB1 : VB0);
        const uint32_t kofs = (t & 1) ? KB1 : KB0;
        const char* kc = smc + kofs + g8 * 16 + tig * 4;

        #pragma unroll
        for (int p4 = 0; p4 < 8; p4++) {
            // ---- two S-MMAs over 16 j (C init = -16 -> e = 2^(s'-16)) ----
            uint32_t kf0 = *(const uint32_t*)(kc + p4 * 256);
            uint32_t kf1 = *(const uint32_t*)(kc + p4 * 256 + 128);
            float sA[4] = {NS, NS, NS, NS};
            float sB[4] = {NS, NS, NS, NS};
            mma_f16k8(sA, qa0, qa1, kf0);
            mma_f16k8(sB, qa0, qa1, kf1);

            // ---- exp2, scalar Z accumulation, pack to fp16 A-frags ----
            float e0 = ex2(sA[0]), e1 = ex2(sA[1]);
            float e2 = ex2(sA[2]), e3 = ex2(sA[3]);
            float f0 = ex2(sB[0]), f1 = ex2(sB[1]);
            float f2 = ex2(sB[2]), f3 = ex2(sB[3]);
            zr0 += (e0 + e1) + (f0 + f1);    // row g
            zr1 += (e2 + e3) + (f2 + f3);    // row g+8
            uint32_t a0 = packh(e0, e1);
            uint32_t a1 = packh(e2, e3);
            uint32_t a2 = packh(f0, f1);
            uint32_t a3 = packh(f2, f3);

            // ---- V B-frags via ldmatrix, 8 PV MMAs ----
            const uint32_t lmbase = vbuf + lm_off + (uint32_t)(p4 * 2304);
            #pragma unroll
            for (int np = 0; np < 4; np++) {
                uint32_t r0, r1, r2, r3;
                ldsm_x4t(r0, r1, r2, r3, lmbase + np * 32);
                mma_f16(acc[np * 2],     a0, a1, a2, a3, r0, r1);
                mma_f16(acc[np * 2 + 1], a0, a1, a2, a3, r2, r3);
            }
        }
        __syncthreads();
    }

    // Z: reduce over the 4 tig lanes (j-partitions) of each group
    zr0 += __shfl_xor_sync(0xffffffffu, zr0, 1);
    zr0 += __shfl_xor_sync(0xffffffffu, zr0, 2);
    zr1 += __shfl_xor_sync(0xffffffffu, zr1, 1);
    zr1 += __shfl_xor_sync(0xffffffffu, zr1, 2);

    // ---- epilogue: stage fragments, normalize, coalesced writes ----
    float* out_s = smem;          // [64][129]
    float* z_s   = smem + ZOFF;   // [128]

    #pragma unroll
    for (int ng = 0; ng < 8; ng++) {
        int c = ng * 8 + 2 * tig;
        int i = wid * 16 + g8;
        out_s[c * 129 + i]           = acc[ng][0];
        out_s[(c + 1) * 129 + i]     = acc[ng][1];
        out_s[c * 129 + i + 8]       = acc[ng][2];
        out_s[(c + 1) * 129 + i + 8] = acc[ng][3];
    }
    if (tig == 0) {
        z_s[wid * 16 + g8]     = zr0;
        z_s[wid * 16 + g8 + 8] = zr1;
    }
    __syncthreads();
    if (tid < 128) z_s[tid] = 1.0f / z_s[tid];
    __syncthreads();

    const float gm = gamma[0];
    #pragma unroll
    for (int r = 0; r < 32; r++) {
        int e  = r * 256 + tid;
        int c  = e >> 7;
        int ii = e & 127;
        size_t gi = ((size_t)(b * CH + c)) * NPIX + i0g + ii;
        out[gi] = fmaf(gm * out_s[c * 129 + ii], z_s[ii], x[gi]);
    }
}

// ---------------------------------------------------------------------------
extern "C" void kernel_launch(void* const* d_in, const int* in_sizes, int n_in,
                              void* d_out, int out_size)
{
    const float* x     = (const float*)d_in[0];
    const float* wq    = (const float*)d_in[1];
    const float* bq    = (const float*)d_in[2];
    const float* wk    = (const float*)d_in[3];
    const float* bk    = (const float*)d_in[4];
    const float* wv    = (const float*)d_in[5];
    const float* bv    = (const float*)d_in[6];
    const float* gamma = (const float*)d_in[7];
    float* out = (float*)d_out;

    cudaFuncSetAttribute(fused_kernel,
                         cudaFuncAttributeMaxDynamicSharedMemorySize,
                         SMEM_BYTES);

    fused_kernel<<<dim3(NPIX / TQ, BATCH), 256, SMEM_BYTES>>>(
        x, wq, bq, wk, bk, wv, bv, gamma, out);
}